// round 13
// baseline (speedup 1.0000x reference)
#include <cuda_runtime.h>

typedef unsigned long long u64;

#define BB 2
#define HH 8
#define SS 4096
#define DD 64
#define HIDN 512
#define NHH 4
#define NCH 256
#define CHK 64

// ---------------- scratch (device globals; no allocations allowed) ----------
__device__ float g_q[BB*HH*SS*DD];
__device__ float g_k[BB*HH*SS*DD];
__device__ float g_v[BB*HH*SS*DD];
__device__ unsigned char g_bq[BB*HH*NHH*SS];
__device__ unsigned char g_bk[BB*HH*NHH*SS];
__device__ int g_sq[BB*HH*NHH*SS];
__device__ int g_sk[BB*HH*NHH*SS];
__device__ int g_undo[BB*HH*NHH*SS];
__device__ float g_osort[BB*HH*NHH*SS*DD];   // 64 MB
__device__ float g_lsort[BB*HH*NHH*SS];

// ---------------- packed f32x2 helpers --------------------------------------
__device__ __forceinline__ void fma2(u64 &d, u64 a, u64 b) {
    asm("fma.rn.f32x2 %0, %1, %2, %0;" : "+l"(d) : "l"(a), "l"(b));
}
__device__ __forceinline__ u64 pack2(float x, float y) {
    u64 r; asm("mov.b64 %0, {%1, %2};" : "=l"(r) : "f"(x), "f"(y)); return r;
}
__device__ __forceinline__ float2 unpack2(u64 a) {
    float x, y; asm("mov.b64 {%0, %1}, %2;" : "=f"(x), "=f"(y) : "l"(a));
    return make_float2(x, y);
}

// ---------------- 1) QKV GEMMs: 128x128 tile, double-buffered ----------------
// thread (tx=tid&15, ty=tid>>4) owns rows m0+ty*8+{0..7} (as 4 f32x2 pairs),
// cols n0+tx*8+{0..7}.
__global__ __launch_bounds__(256) void gemm_kernel(
        const float* __restrict__ dec, const float* __restrict__ hid,
        const float* __restrict__ wqk, const float* __restrict__ wv) {
    int z = blockIdx.z;
    const float* X = (z == 0) ? dec : hid;
    const float* W = (z == 2) ? wv : wqk;
    float* out = (z == 0) ? g_q : (z == 1) ? g_k : g_v;

    __shared__ float As[2][16][128];   // [k][m]
    __shared__ float Bs[2][16][128];   // [k][n]
    int tid = threadIdx.x;
    int tx = tid & 15, ty = tid >> 4;
    int n0 = blockIdx.x * 128, m0 = blockIdx.y * 128;
    int arow = tid >> 1, acol = (tid & 1) * 8;      // A: 128 rows x 16 k
    int brow = tid >> 4, bcol = (tid & 15) * 8;     // B: 16 k x 128 n

    u64 acc[4][8];
#pragma unroll
    for (int i = 0; i < 4; i++)
#pragma unroll
        for (int j = 0; j < 8; j++) acc[i][j] = 0ULL;

    const float* Abase = X + (size_t)(m0 + arow) * HIDN + acol;
    const float* Bbase = W + (size_t)brow * HIDN + n0 + bcol;

    // prologue: chunk 0 -> buf0; prefetch chunk 1 into regs
    float4 ra0 = *(const float4*)(Abase);
    float4 ra1 = *(const float4*)(Abase + 4);
    float4 rb0 = *(const float4*)(Bbase);
    float4 rb1 = *(const float4*)(Bbase + 4);
    As[0][acol+0][arow]=ra0.x; As[0][acol+1][arow]=ra0.y; As[0][acol+2][arow]=ra0.z; As[0][acol+3][arow]=ra0.w;
    As[0][acol+4][arow]=ra1.x; As[0][acol+5][arow]=ra1.y; As[0][acol+6][arow]=ra1.z; As[0][acol+7][arow]=ra1.w;
    *(float4*)&Bs[0][brow][bcol] = rb0;
    *(float4*)&Bs[0][brow][bcol+4] = rb1;
    ra0 = *(const float4*)(Abase + 16);
    ra1 = *(const float4*)(Abase + 20);
    rb0 = *(const float4*)(Bbase + (size_t)16 * HIDN);
    rb1 = *(const float4*)(Bbase + (size_t)16 * HIDN + 4);
    __syncthreads();

    int s = 0;
#pragma unroll 1
    for (int ch = 0; ch < HIDN/16; ch++, s ^= 1) {
        if (ch + 1 < HIDN/16) {
            int so = s ^ 1;
            As[so][acol+0][arow]=ra0.x; As[so][acol+1][arow]=ra0.y; As[so][acol+2][arow]=ra0.z; As[so][acol+3][arow]=ra0.w;
            As[so][acol+4][arow]=ra1.x; As[so][acol+5][arow]=ra1.y; As[so][acol+6][arow]=ra1.z; As[so][acol+7][arow]=ra1.w;
            *(float4*)&Bs[so][brow][bcol] = rb0;
            *(float4*)&Bs[so][brow][bcol+4] = rb1;
        }
        if (ch + 2 < HIDN/16) {
            int k0 = (ch + 2) * 16;
            ra0 = *(const float4*)(Abase + k0);
            ra1 = *(const float4*)(Abase + k0 + 4);
            rb0 = *(const float4*)(Bbase + (size_t)k0 * HIDN);
            rb1 = *(const float4*)(Bbase + (size_t)k0 * HIDN + 4);
        }
#pragma unroll
        for (int kk = 0; kk < 16; kk++) {
            ulonglong2 a01 = *(const ulonglong2*)&As[s][kk][ty*8];
            ulonglong2 a23 = *(const ulonglong2*)&As[s][kk][ty*8 + 4];
            float4 bv0 = *(const float4*)&Bs[s][kk][tx*8];
            float4 bv1 = *(const float4*)&Bs[s][kk][tx*8 + 4];
            u64 a2[4] = { a01.x, a01.y, a23.x, a23.y };
            u64 b2[8] = { pack2(bv0.x,bv0.x), pack2(bv0.y,bv0.y), pack2(bv0.z,bv0.z), pack2(bv0.w,bv0.w),
                          pack2(bv1.x,bv1.x), pack2(bv1.y,bv1.y), pack2(bv1.z,bv1.z), pack2(bv1.w,bv1.w) };
#pragma unroll
            for (int ii = 0; ii < 4; ii++)
#pragma unroll
                for (int j = 0; j < 8; j++) fma2(acc[ii][j], a2[ii], b2[j]);
        }
        __syncthreads();
    }
    int h = (n0 + tx*8) >> 6;
    int d = (n0 + tx*8) & 63;
#pragma unroll
    for (int ii = 0; ii < 4; ii++) {
        float2 c[8];
#pragma unroll
        for (int j = 0; j < 8; j++) c[j] = unpack2(acc[ii][j]);
        int m = m0 + ty*8 + 2*ii;
        int b = m >> 12, sx = m & (SS - 1);
        float* o0 = out + ((size_t)(b*HH + h)*SS + sx)*DD + d;
        *(float4*)o0       = make_float4(c[0].x, c[1].x, c[2].x, c[3].x);
        *(float4*)(o0 + 4) = make_float4(c[4].x, c[5].x, c[6].x, c[7].x);
        int m1 = m + 1; int b1 = m1 >> 12, s1 = m1 & (SS - 1);
        float* o1 = out + ((size_t)(b1*HH + h)*SS + s1)*DD + d;
        *(float4*)o1       = make_float4(c[0].y, c[1].y, c[2].y, c[3].y);
        *(float4*)(o1 + 4) = make_float4(c[4].y, c[5].y, c[6].y, c[7].y);
    }
}

// ---------------- 2) LSH hash as tiled GEMM + fused argmax ------------------
#define RSN 4104          // n-stride in floats
#define VSS 65            // v tile token stride
__global__ __launch_bounds__(256) void hash_kernel(const float* __restrict__ rot) {
    extern __shared__ float sh[];
    float* rs = sh;                 // rs[n*RSN + d*64 + r]
    float* vs = sh + NHH*RSN;       // vs[tok*VSS + d]
    int tid = threadIdx.x;
    int h = blockIdx.y;
    int b = blockIdx.z >> 1, tensor = blockIdx.z & 1;

    const float* rsrc = rot + (size_t)h * (64*NHH*64);
    for (int idx = tid; idx < NHH*64*64; idx += 256) {
        int r = idx & 63; int dn = idx >> 6;   // dn = d*NHH + n
        int n = dn & 3, d = dn >> 2;
        rs[n*RSN + d*64 + r] = rsrc[idx];
    }
    int tok0 = blockIdx.x * 64;
    const float* vbase = (tensor == 0 ? g_q : g_k) + ((size_t)(b*HH + h)*SS + tok0)*DD;
    for (int idx = tid; idx < 64*(DD/4); idx += 256) {
        int tok = idx >> 4, d4 = (idx & 15) * 4;
        float4 t4 = *(const float4*)(vbase + tok*DD + d4);
        vs[tok*VSS + d4 + 0] = t4.x; vs[tok*VSS + d4 + 1] = t4.y;
        vs[tok*VSS + d4 + 2] = t4.z; vs[tok*VSS + d4 + 3] = t4.w;
    }
    __syncthreads();

    int tq = tid >> 4, tr = tid & 15;
    int n = tr >> 2, rg = tr & 3;
    const float* rbase = rs + n*RSN + rg*16;

    u64 acc[4][8];
#pragma unroll
    for (int i = 0; i < 4; i++)
#pragma unroll
        for (int j = 0; j < 8; j++) acc[i][j] = 0ULL;

    for (int d = 0; d < 64; d++) {
        u64 b2[8];
        const u64* rp = (const u64*)(rbase + d*64);
#pragma unroll
        for (int j = 0; j < 8; j++) b2[j] = rp[j];
#pragma unroll
        for (int i = 0; i < 4; i++) {
            float vv = vs[(tq*4 + i)*VSS + d];
            u64 a2 = pack2(vv, vv);
#pragma unroll
            for (int j = 0; j < 8; j++) fma2(acc[i][j], a2, b2[j]);
        }
    }

    unsigned char* outb = (tensor == 0 ? g_bq : g_bk);
#pragma unroll
    for (int i = 0; i < 4; i++) {
        float bpv = -1e30f, bnv = -1e30f; int bpi = 0, bni = 0;
#pragma unroll
        for (int j = 0; j < 8; j++) {
            float2 a = unpack2(acc[i][j]);
            int r0 = rg*16 + 2*j;
            if (a.x > bpv)  { bpv = a.x;  bpi = r0; }
            if (a.y > bpv)  { bpv = a.y;  bpi = r0 + 1; }
            if (-a.x > bnv) { bnv = -a.x; bni = r0; }
            if (-a.y > bnv) { bnv = -a.y; bni = r0 + 1; }
        }
#pragma unroll
        for (int off = 1; off < 4; off <<= 1) {
            float ov = __shfl_down_sync(0xffffffffu, bpv, off);
            int   oi = __shfl_down_sync(0xffffffffu, bpi, off);
            if (ov > bpv) { bpv = ov; bpi = oi; }
            float on = __shfl_down_sync(0xffffffffu, bnv, off);
            int   oj = __shfl_down_sync(0xffffffffu, bni, off);
            if (on > bnv) { bnv = on; bni = oj; }
        }
        if (rg == 0) {
            int bucket = (bpv >= bnv) ? bpi : 64 + bni;  // pos side wins ties
            outb[((size_t)(b*HH + h)*NHH + n)*SS + tok0 + tq*4 + i] = (unsigned char)bucket;
        }
    }
}

// ---------------- 3) warp-parallel stable counting sort ---------------------
__global__ __launch_bounds__(256) void sort_kernel() {
    __shared__ unsigned char sb[SS];
    __shared__ int wcnt[8][128];
    __shared__ int woff[8][128];
    __shared__ int tot[128];
    int combo = blockIdx.x;
    int tensor = blockIdx.y;
    const unsigned char* bg = (tensor == 0 ? g_bq : g_bk) + (size_t)combo * SS;
    int t = threadIdx.x, w = t >> 5, l = t & 31;
    for (int i = t; i < SS/4; i += 256)
        ((unsigned int*)sb)[i] = ((const unsigned int*)bg)[i];
    if (t < 128) {
#pragma unroll
        for (int ww = 0; ww < 8; ww++) wcnt[ww][t] = 0;
    }
    __syncthreads();
    int seg = w * 512;
    int myb[16];
#pragma unroll
    for (int it = 0; it < 16; it++) {
        int bkt = sb[seg + it*32 + l];
        myb[it] = bkt;
        unsigned mask = __match_any_sync(0xffffffffu, (unsigned)bkt);
        if ((__ffs(mask) - 1) == l) wcnt[w][bkt] += __popc(mask);
    }
    __syncthreads();
    if (t < 128) {
        int s = 0;
#pragma unroll
        for (int ww = 0; ww < 8; ww++) s += wcnt[ww][t];
        tot[t] = s;
    }
    __syncthreads();
    if (t == 0) {
        int a = 0;
        for (int bkt = 0; bkt < 128; bkt++) { int c = tot[bkt]; tot[bkt] = a; a += c; }
    }
    __syncthreads();
    if (t < 128) {
        int run = tot[t];
#pragma unroll
        for (int ww = 0; ww < 8; ww++) { int c = wcnt[ww][t]; woff[ww][t] = run; run += c; }
    }
    __syncthreads();
    int* sorted = (tensor == 0 ? g_sq : g_sk) + (size_t)combo * SS;
    int* undo = g_undo + (size_t)combo * SS;
#pragma unroll
    for (int it = 0; it < 16; it++) {
        int p = seg + it*32 + l;
        int bkt = myb[it];
        unsigned mask = __match_any_sync(0xffffffffu, (unsigned)bkt);
        int leader = __ffs(mask) - 1;
        int rank = __popc(mask & ((1u << l) - 1u));
        int base = 0;
        if (l == leader) { base = woff[w][bkt]; woff[w][bkt] = base + __popc(mask); }
        base = __shfl_sync(mask, base, leader);
        sorted[base + rank] = p;
        if (tensor == 1) undo[p] = base + rank;
    }
}

// ---------------- 4) chunk attention (float4-quad probs layout) -------------
#define QSO 0
#define KTO 4096
#define VTO 12288
#define PBO 0
#define PBQ 260
#define OBO 0
#define OSTR 68
#define IDXO 20480
#define SMEMF 20672

__global__ __launch_bounds__(256, 2) void attn_kernel() {
    extern __shared__ float sm[];
    int tid = threadIdx.x;
    int c = blockIdx.x;          // global chunk 0..255 (ring across rounds)
    int bh = blockIdx.y;         // b*H + h
    int n = c >> 6, cl = c & 63;
    int cp = (c + NCH - 1) & (NCH - 1);
    int np = cp >> 6, clp = cp & 63;

    const int* sq_n = g_sq + ((size_t)bh*NHH + n)*SS + cl*64;
    const int* sq_p = g_sq + ((size_t)bh*NHH + np)*SS + clp*64;
    const int* sk_n = g_sk + ((size_t)bh*NHH + n)*SS + cl*64;
    const int* sk_p = g_sk + ((size_t)bh*NHH + np)*SS + clp*64;

    int* qidx = (int*)&sm[IDXO];
    int* kidx = qidx + 64;
    if (tid < 64)       { int s = sq_n[tid]; qidx[tid] = s; kidx[64 + tid] = s; }
    else if (tid < 128) { kidx[tid - 64] = sq_p[tid - 64]; }

    // q tile [64 x 64]
    {
        int r = tid >> 2, dq = (tid & 3) * 4;
        const float* src = g_q + ((size_t)bh*SS + sq_n[r])*DD;
#pragma unroll
        for (int g = 0; g < 4; g++) {
            int d = dq + g*16;
            *(float4*)&sm[QSO + r*64 + d] = *(const float4*)&src[d];
        }
    }
    // K (normalize, dim-major float4 tiles) by threads 0..127; V^T by 128..255
    if (tid < 128) {
        int j = tid;
        int s = (j < 64) ? sk_p[j] : sk_n[j - 64];
        const float4* ksrc = (const float4*)(g_k + ((size_t)bh*SS + s)*DD);
        float ssq = 0.f;
#pragma unroll
        for (int g = 0; g < 16; g++) {
            float4 t = ksrc[g];
            ssq += t.x*t.x + t.y*t.y + t.z*t.z + t.w*t.w;
        }
        float sc = rsqrtf(ssq * (1.0f/64.0f) + 1e-6f) * 0.125f;
#pragma unroll
        for (int g = 0; g < 16; g++) {
            float4 t = ksrc[g];
            *(float4*)&sm[KTO + (g*128 + j)*4] = make_float4(t.x*sc, t.y*sc, t.z*sc, t.w*sc);
        }
    } else {
        int j = tid - 128;
        int s = (j < 64) ? sk_p[j] : sk_n[j - 64];
        const float4* vsrc = (const float4*)(g_v + ((size_t)bh*SS + s)*DD);
#pragma unroll
        for (int g = 0; g < 16; g++) {
            float4 t = vsrc[g];
            sm[VTO + (4*g+0)*128 + j] = t.x;
            sm[VTO + (4*g+1)*128 + j] = t.y;
            sm[VTO + (4*g+2)*128 + j] = t.z;
            sm[VTO + (4*g+3)*128 + j] = t.w;
        }
    }
    __syncthreads();

    int w = tid >> 5, l = tid & 31;

    // QK^T: warp w owns rows w*8..w*8+7; lane owns cols l+32*jj
    u64 acc[8][4];
#pragma unroll
    for (int i = 0; i < 8; i++)
#pragma unroll
        for (int j = 0; j < 4; j++) acc[i][j] = 0ULL;
#pragma unroll 4
    for (int dp2 = 0; dp2 < 16; dp2++) {
        ulonglong2 kk[4];
#pragma unroll
        for (int jj = 0; jj < 4; jj++)
            kk[jj] = *(const ulonglong2*)&sm[KTO + (dp2*128 + l + 32*jj)*4];
#pragma unroll
        for (int rr = 0; rr < 8; rr++) {
            ulonglong2 qq = *(const ulonglong2*)&sm[QSO + (w*8 + rr)*64 + dp2*4];
#pragma unroll
            for (int jj = 0; jj < 4; jj++) {
                fma2(acc[rr][jj], qq.x, kk[jj].x);
                fma2(acc[rr][jj], qq.y, kk[jj].y);
            }
        }
    }
    __syncthreads();   // q/k tiles free; probs region becomes writable

    // mask + softmax per row; write probs in float4-quad layout; emit logsumexp
#pragma unroll
    for (int rr = 0; rr < 8; rr++) {
        int i = w*8 + rr;
        int qi = qidx[i];
        float dv[4];
#pragma unroll
        for (int jj = 0; jj < 4; jj++) {
            float2 a = unpack2(acc[rr][jj]);
            float t = a.x + a.y;
            dv[jj] = (qi != kidx[l + 32*jj]) ? t : -1e5f;
        }
        float m = fmaxf(fmaxf(dv[0], dv[1]), fmaxf(dv[2], dv[3]));
#pragma unroll
        for (int off = 16; off; off >>= 1) m = fmaxf(m, __shfl_xor_sync(0xffffffffu, m, off));
        float p[4], ssum = 0.f;
#pragma unroll
        for (int jj = 0; jj < 4; jj++) { p[jj] = expf(dv[jj] - m); ssum += p[jj]; }
#pragma unroll
        for (int off = 16; off; off >>= 1) ssum += __shfl_xor_sync(0xffffffffu, ssum, off);
        float inv = 1.f / ssum;
#pragma unroll
        for (int jj = 0; jj < 4; jj++) {
            int cq = l + 32*jj;                 // col 0..127
            sm[PBO + (cq >> 2)*PBQ + i*4 + (cq & 3)] = p[jj] * inv;
        }
        if (l == 0) g_lsort[(size_t)bh*(NHH*SS) + c*64 + i] = logf(ssum) + m;
    }
    __syncthreads();

    // PV: lane owns rows l and l+32; warp owns dims w*8..w*8+7; jq over ALL 32 quads
    u64 o0[8], o1[8];
#pragma unroll
    for (int dd = 0; dd < 8; dd++) { o0[dd] = 0ULL; o1[dd] = 0ULL; }
#pragma unroll 4
    for (int jq = 0; jq < 32; jq++) {
        ulonglong2 pr0 = *(const ulonglong2*)&sm[PBO + jq*PBQ + l*4];
        ulonglong2 pr1 = *(const ulonglong2*)&sm[PBO + jq*PBQ + (l+32)*4];
#pragma unroll
        for (int dd = 0; dd < 8; dd++) {
            ulonglong2 vv = *(const ulonglong2*)&sm[VTO + (w*8 + dd)*128 + jq*4];
            fma2(o0[dd], pr0.x, vv.x);
            fma2(o0[dd], pr0.y, vv.y);
            fma2(o1[dd], pr1.x, vv.x);
            fma2(o1[dd], pr1.y, vv.y);
        }
    }
    __syncthreads();   // probs free; out-stage region writable
#pragma unroll
    for (int dd = 0; dd < 8; dd++) {
        float2 a = unpack2(o0[dd]); sm[OBO + l*OSTR + w*8 + dd] = a.x + a.y;
        float2 b2 = unpack2(o1[dd]); sm[OBO + (l+32)*OSTR + w*8 + dd] = b2.x + b2.y;
    }
    __syncthreads();
    {
        int r = tid >> 2, dq = (tid & 3) * 4;
        float* dst = g_osort + ((size_t)bh*(NHH*SS) + c*64 + r)*DD;
#pragma unroll
        for (int g = 0; g < 4; g++) {
            int d = dq + g*16;
            *(float4*)&dst[d] = *(const float4*)&sm[OBO + r*OSTR + d];
        }
    }
}

// ---------------- 5) key-side undo + combine rounds -------------------------
__global__ __launch_bounds__(256) void combine_kernel(float* __restrict__ out) {
    int row = blockIdx.x * 8 + (threadIdx.x >> 5);  // b*H*S rows
    int l = threadIdx.x & 31;
    int bh = row >> 12;
    int s = row & (SS - 1);
    int b = bh >> 3, h = bh & 7;
    float lg[NHH]; int up[NHH];
#pragma unroll
    for (int n = 0; n < NHH; n++) {
        int u = g_undo[((size_t)bh*NHH + n)*SS + s];
        up[n] = u;
        lg[n] = g_lsort[(size_t)bh*(NHH*SS) + n*SS + u];
    }
    float m = fmaxf(fmaxf(lg[0], lg[1]), fmaxf(lg[2], lg[3]));
    float w[NHH], wsum = 0.f;
#pragma unroll
    for (int n = 0; n < NHH; n++) { w[n] = expf(lg[n] - m); wsum += w[n]; }
    float inv = 1.f / wsum;
    float2 acc = make_float2(0.f, 0.f);
#pragma unroll
    for (int n = 0; n < NHH; n++) {
        float2 o = *(const float2*)&g_osort[((size_t)bh*(NHH*SS) + n*SS + up[n])*DD + l*2];
        acc.x += w[n]*o.x; acc.y += w[n]*o.y;
    }
    acc.x *= inv; acc.y *= inv;
    *(float2*)&out[((size_t)(b*SS + s))*(HH*DD) + h*DD + l*2] = acc;
}

// ---------------- launch -----------------------------------------------------
#define HASH_SMEM ((NHH*RSN + 64*VSS) * 4)

extern "C" void kernel_launch(void* const* d_in, const int* in_sizes, int n_in,
                              void* d_out, int out_size) {
    const float* dec = (const float*)d_in[0];
    const float* hid = (const float*)d_in[1];
    const float* wqk = (const float*)d_in[2];
    const float* wv  = (const float*)d_in[3];
    const float* rot = (const float*)d_in[4];
    float* out = (float*)d_out;

    cudaFuncSetAttribute(hash_kernel, cudaFuncAttributeMaxDynamicSharedMemorySize, HASH_SMEM);
    cudaFuncSetAttribute(attn_kernel, cudaFuncAttributeMaxDynamicSharedMemorySize, SMEMF*4);

    gemm_kernel<<<dim3(4, 64, 3), 256>>>(dec, hid, wqk, wv);
    hash_kernel<<<dim3(SS/64, HH, BB*2), 256, HASH_SMEM>>>(rot);
    sort_kernel<<<dim3(BB*HH*NHH, 2), 256>>>();
    attn_kernel<<<dim3(NCH, BB*HH), 256, SMEMF*4>>>();
    combine_kernel<<<BB*HH*SS/8, 256>>>(out);
}

// round 14
// speedup vs baseline: 1.0490x; 1.0490x over previous
#include <cuda_runtime.h>

typedef unsigned long long u64;

#define BB 2
#define HH 8
#define SS 4096
#define DD 64
#define HIDN 512
#define NHH 4
#define NCH 256
#define CHK 64

// ---------------- scratch (device globals; no allocations allowed) ----------
__device__ float g_q[BB*HH*SS*DD];
__device__ float g_k[BB*HH*SS*DD];
__device__ float g_v[BB*HH*SS*DD];
__device__ unsigned char g_bq[BB*HH*NHH*SS];
__device__ unsigned char g_bk[BB*HH*NHH*SS];
__device__ int g_sq[BB*HH*NHH*SS];
__device__ int g_sk[BB*HH*NHH*SS];
__device__ int g_undo[BB*HH*NHH*SS];
__device__ float g_osort[BB*HH*NHH*SS*DD];   // 64 MB
__device__ float g_lsort[BB*HH*NHH*SS];

// ---------------- packed f32x2 helpers --------------------------------------
__device__ __forceinline__ void fma2(u64 &d, u64 a, u64 b) {
    asm("fma.rn.f32x2 %0, %1, %2, %0;" : "+l"(d) : "l"(a), "l"(b));
}
__device__ __forceinline__ u64 pack2(float x, float y) {
    u64 r; asm("mov.b64 %0, {%1, %2};" : "=l"(r) : "f"(x), "f"(y)); return r;
}
__device__ __forceinline__ float2 unpack2(u64 a) {
    float x, y; asm("mov.b64 {%0, %1}, %2;" : "=f"(x), "=f"(y) : "l"(a));
    return make_float2(x, y);
}

// ---------------- 1) QKV GEMMs: 128x64 tile, double-buffered (R12 version) --
__global__ __launch_bounds__(256) void gemm_kernel(
        const float* __restrict__ dec, const float* __restrict__ hid,
        const float* __restrict__ wqk, const float* __restrict__ wv) {
    int z = blockIdx.z;
    const float* X = (z == 0) ? dec : hid;
    const float* W = (z == 2) ? wv : wqk;
    float* out = (z == 0) ? g_q : (z == 1) ? g_k : g_v;

    __shared__ float As[2][16][128];
    __shared__ float Bs[2][16][64];
    int tid = threadIdx.x;
    int tx = tid & 15, ty = tid >> 4;
    int m0 = blockIdx.y * 128, n0 = blockIdx.x * 64;
    int arow = tid >> 1, acol = (tid & 1) * 8;
    int brow = tid >> 4, bcol = (tid & 15) * 4;

    u64 acc[4][4];
#pragma unroll
    for (int i = 0; i < 4; i++)
#pragma unroll
        for (int j = 0; j < 4; j++) acc[i][j] = 0ULL;

    const float* Abase = X + (size_t)(m0 + arow) * HIDN + acol;
    const float* Bbase = W + (size_t)brow * HIDN + n0 + bcol;

    float4 ra0 = *(const float4*)(Abase);
    float4 ra1 = *(const float4*)(Abase + 4);
    float4 rb0 = *(const float4*)(Bbase);
    As[0][acol+0][arow]=ra0.x; As[0][acol+1][arow]=ra0.y; As[0][acol+2][arow]=ra0.z; As[0][acol+3][arow]=ra0.w;
    As[0][acol+4][arow]=ra1.x; As[0][acol+5][arow]=ra1.y; As[0][acol+6][arow]=ra1.z; As[0][acol+7][arow]=ra1.w;
    *(float4*)&Bs[0][brow][bcol] = rb0;
    ra0 = *(const float4*)(Abase + 16);
    ra1 = *(const float4*)(Abase + 20);
    rb0 = *(const float4*)(Bbase + (size_t)16 * HIDN);
    __syncthreads();

    int s = 0;
#pragma unroll 1
    for (int ch = 0; ch < HIDN/16; ch++, s ^= 1) {
        if (ch + 1 < HIDN/16) {
            int so = s ^ 1;
            As[so][acol+0][arow]=ra0.x; As[so][acol+1][arow]=ra0.y; As[so][acol+2][arow]=ra0.z; As[so][acol+3][arow]=ra0.w;
            As[so][acol+4][arow]=ra1.x; As[so][acol+5][arow]=ra1.y; As[so][acol+6][arow]=ra1.z; As[so][acol+7][arow]=ra1.w;
            *(float4*)&Bs[so][brow][bcol] = rb0;
        }
        if (ch + 2 < HIDN/16) {
            int k0 = (ch + 2) * 16;
            ra0 = *(const float4*)(Abase + k0);
            ra1 = *(const float4*)(Abase + k0 + 4);
            rb0 = *(const float4*)(Bbase + (size_t)k0 * HIDN);
        }
#pragma unroll
        for (int kk = 0; kk < 16; kk++) {
            u64 a2[4];
#pragma unroll
            for (int ii = 0; ii < 4; ii++) a2[ii] = *(const u64*)&As[s][kk][ty*8 + 2*ii];
            float4 bv = *(const float4*)&Bs[s][kk][tx*4];
            u64 b2[4] = { pack2(bv.x,bv.x), pack2(bv.y,bv.y), pack2(bv.z,bv.z), pack2(bv.w,bv.w) };
#pragma unroll
            for (int ii = 0; ii < 4; ii++)
#pragma unroll
                for (int j = 0; j < 4; j++) fma2(acc[ii][j], a2[ii], b2[j]);
        }
        __syncthreads();
    }
    int h = n0 >> 6;
#pragma unroll
    for (int ii = 0; ii < 4; ii++) {
        float2 c0 = unpack2(acc[ii][0]), c1 = unpack2(acc[ii][1]);
        float2 c2 = unpack2(acc[ii][2]), c3 = unpack2(acc[ii][3]);
        int m = m0 + ty*8 + 2*ii;
        int b = m >> 12, sx = m & (SS - 1);
        float* o0 = out + ((size_t)(b*HH + h)*SS + sx)*DD + tx*4;
        *(float4*)o0 = make_float4(c0.x, c1.x, c2.x, c3.x);
        int m1 = m + 1; int b1 = m1 >> 12, s1 = m1 & (SS - 1);
        float* o1 = out + ((size_t)(b1*HH + h)*SS + s1)*DD + tx*4;
        *(float4*)o1 = make_float4(c0.y, c1.y, c2.y, c3.y);
    }
}

// ---------------- 2) LSH hash as tiled GEMM + fused argmax ------------------
#define RSN 4104          // n-stride in floats
#define VSS 65            // v tile token stride
__global__ __launch_bounds__(256) void hash_kernel(const float* __restrict__ rot) {
    extern __shared__ float sh[];
    float* rs = sh;                 // rs[n*RSN + d*64 + r]
    float* vs = sh + NHH*RSN;       // vs[tok*VSS + d]
    int tid = threadIdx.x;
    int h = blockIdx.y;
    int b = blockIdx.z >> 1, tensor = blockIdx.z & 1;

    const float* rsrc = rot + (size_t)h * (64*NHH*64);
    for (int idx = tid; idx < NHH*64*64; idx += 256) {
        int r = idx & 63; int dn = idx >> 6;   // dn = d*NHH + n
        int n = dn & 3, d = dn >> 2;
        rs[n*RSN + d*64 + r] = rsrc[idx];
    }
    int tok0 = blockIdx.x * 64;
    const float* vbase = (tensor == 0 ? g_q : g_k) + ((size_t)(b*HH + h)*SS + tok0)*DD;
    for (int idx = tid; idx < 64*(DD/4); idx += 256) {
        int tok = idx >> 4, d4 = (idx & 15) * 4;
        float4 t4 = *(const float4*)(vbase + tok*DD + d4);
        vs[tok*VSS + d4 + 0] = t4.x; vs[tok*VSS + d4 + 1] = t4.y;
        vs[tok*VSS + d4 + 2] = t4.z; vs[tok*VSS + d4 + 3] = t4.w;
    }
    __syncthreads();

    int tq = tid >> 4, tr = tid & 15;
    int n = tr >> 2, rg = tr & 3;
    const float* rbase = rs + n*RSN + rg*16;

    u64 acc[4][8];
#pragma unroll
    for (int i = 0; i < 4; i++)
#pragma unroll
        for (int j = 0; j < 8; j++) acc[i][j] = 0ULL;

    for (int d = 0; d < 64; d++) {
        u64 b2[8];
        const u64* rp = (const u64*)(rbase + d*64);
#pragma unroll
        for (int j = 0; j < 8; j++) b2[j] = rp[j];
#pragma unroll
        for (int i = 0; i < 4; i++) {
            float vv = vs[(tq*4 + i)*VSS + d];
            u64 a2 = pack2(vv, vv);
#pragma unroll
            for (int j = 0; j < 8; j++) fma2(acc[i][j], a2, b2[j]);
        }
    }

    unsigned char* outb = (tensor == 0 ? g_bq : g_bk);
#pragma unroll
    for (int i = 0; i < 4; i++) {
        float bpv = -1e30f, bnv = -1e30f; int bpi = 0, bni = 0;
#pragma unroll
        for (int j = 0; j < 8; j++) {
            float2 a = unpack2(acc[i][j]);
            int r0 = rg*16 + 2*j;
            if (a.x > bpv)  { bpv = a.x;  bpi = r0; }
            if (a.y > bpv)  { bpv = a.y;  bpi = r0 + 1; }
            if (-a.x > bnv) { bnv = -a.x; bni = r0; }
            if (-a.y > bnv) { bnv = -a.y; bni = r0 + 1; }
        }
#pragma unroll
        for (int off = 1; off < 4; off <<= 1) {
            float ov = __shfl_down_sync(0xffffffffu, bpv, off);
            int   oi = __shfl_down_sync(0xffffffffu, bpi, off);
            if (ov > bpv) { bpv = ov; bpi = oi; }
            float on = __shfl_down_sync(0xffffffffu, bnv, off);
            int   oj = __shfl_down_sync(0xffffffffu, bni, off);
            if (on > bnv) { bnv = on; bni = oj; }
        }
        if (rg == 0) {
            int bucket = (bpv >= bnv) ? bpi : 64 + bni;  // pos side wins ties
            outb[((size_t)(b*HH + h)*NHH + n)*SS + tok0 + tq*4 + i] = (unsigned char)bucket;
        }
    }
}

// ---------------- 3) warp-parallel stable counting sort ---------------------
__global__ __launch_bounds__(256) void sort_kernel() {
    __shared__ unsigned char sb[SS];
    __shared__ int wcnt[8][128];
    __shared__ int woff[8][128];
    __shared__ int tot[128];
    int combo = blockIdx.x;
    int tensor = blockIdx.y;
    const unsigned char* bg = (tensor == 0 ? g_bq : g_bk) + (size_t)combo * SS;
    int t = threadIdx.x, w = t >> 5, l = t & 31;
    for (int i = t; i < SS/4; i += 256)
        ((unsigned int*)sb)[i] = ((const unsigned int*)bg)[i];
    if (t < 128) {
#pragma unroll
        for (int ww = 0; ww < 8; ww++) wcnt[ww][t] = 0;
    }
    __syncthreads();
    int seg = w * 512;
    int myb[16];
#pragma unroll
    for (int it = 0; it < 16; it++) {
        int bkt = sb[seg + it*32 + l];
        myb[it] = bkt;
        unsigned mask = __match_any_sync(0xffffffffu, (unsigned)bkt);
        if ((__ffs(mask) - 1) == l) wcnt[w][bkt] += __popc(mask);
    }
    __syncthreads();
    if (t < 128) {
        int s = 0;
#pragma unroll
        for (int ww = 0; ww < 8; ww++) s += wcnt[ww][t];
        tot[t] = s;
    }
    __syncthreads();
    if (t == 0) {
        int a = 0;
        for (int bkt = 0; bkt < 128; bkt++) { int c = tot[bkt]; tot[bkt] = a; a += c; }
    }
    __syncthreads();
    if (t < 128) {
        int run = tot[t];
#pragma unroll
        for (int ww = 0; ww < 8; ww++) { int c = wcnt[ww][t]; woff[ww][t] = run; run += c; }
    }
    __syncthreads();
    int* sorted = (tensor == 0 ? g_sq : g_sk) + (size_t)combo * SS;
    int* undo = g_undo + (size_t)combo * SS;
#pragma unroll
    for (int it = 0; it < 16; it++) {
        int p = seg + it*32 + l;
        int bkt = myb[it];
        unsigned mask = __match_any_sync(0xffffffffu, (unsigned)bkt);
        int leader = __ffs(mask) - 1;
        int rank = __popc(mask & ((1u << l) - 1u));
        int base = 0;
        if (l == leader) { base = woff[w][bkt]; woff[w][bkt] = base + __popc(mask); }
        base = __shfl_sync(mask, base, leader);
        sorted[base + rank] = p;
        if (tensor == 1) undo[p] = base + rank;
    }
}

// ---------------- 4) chunk attention (float4-quad probs, wide loader) -------
#define QSO 0
#define KTO 4096
#define VTO 12288
#define PBO 0
#define PBQ 260
#define OBO 0
#define OSTR 68
#define IDXO 20480
#define SMEMF 20672

__global__ __launch_bounds__(256, 2) void attn_kernel() {
    extern __shared__ float sm[];
    int tid = threadIdx.x;
    int c = blockIdx.x;          // global chunk 0..255 (ring across rounds)
    int bh = blockIdx.y;         // b*H + h
    int n = c >> 6, cl = c & 63;
    int cp = (c + NCH - 1) & (NCH - 1);
    int np = cp >> 6, clp = cp & 63;

    const int* sq_n = g_sq + ((size_t)bh*NHH + n)*SS + cl*64;
    const int* sq_p = g_sq + ((size_t)bh*NHH + np)*SS + clp*64;
    const int* sk_n = g_sk + ((size_t)bh*NHH + n)*SS + cl*64;
    const int* sk_p = g_sk + ((size_t)bh*NHH + np)*SS + clp*64;

    int* qidx = (int*)&sm[IDXO];
    int* kidx = qidx + 64;
    if (tid < 64)       { int s = sq_n[tid]; qidx[tid] = s; kidx[64 + tid] = s; }
    else if (tid < 128) { kidx[tid - 64] = sq_p[tid - 64]; }

    // q tile [64 x 64]
    {
        int r = tid >> 2, dq = (tid & 3) * 4;
        const float* src = g_q + ((size_t)bh*SS + sq_n[r])*DD;
#pragma unroll
        for (int g = 0; g < 4; g++) {
            int d = dq + g*16;
            *(float4*)&sm[QSO + r*64 + d] = *(const float4*)&src[d];
        }
    }
    // K (normalize) + V^T: all 256 threads, 2 threads per row (half rows each)
    {
        int j = tid >> 1, half = tid & 1;
        int s = (j < 64) ? sk_p[j] : sk_n[j - 64];
        const float4* ksrc = (const float4*)(g_k + ((size_t)bh*SS + s)*DD) + half*8;
        const float4* vsrc = (const float4*)(g_v + ((size_t)bh*SS + s)*DD) + half*8;
        float4 kr[8], vr[8];
        float ssq = 0.f;
#pragma unroll
        for (int g = 0; g < 8; g++) {
            kr[g] = ksrc[g];
            vr[g] = vsrc[g];
            ssq += kr[g].x*kr[g].x + kr[g].y*kr[g].y + kr[g].z*kr[g].z + kr[g].w*kr[g].w;
        }
        ssq += __shfl_xor_sync(0xffffffffu, ssq, 1);   // partner lane, same row
        float sc = rsqrtf(ssq * (1.0f/64.0f) + 1e-6f) * 0.125f;
#pragma unroll
        for (int g = 0; g < 8; g++) {
            int gg = half*8 + g;
            *(float4*)&sm[KTO + (gg*128 + j)*4] =
                make_float4(kr[g].x*sc, kr[g].y*sc, kr[g].z*sc, kr[g].w*sc);
            int d = gg*4;
            sm[VTO + (d+0)*128 + j] = vr[g].x;
            sm[VTO + (d+1)*128 + j] = vr[g].y;
            sm[VTO + (d+2)*128 + j] = vr[g].z;
            sm[VTO + (d+3)*128 + j] = vr[g].w;
        }
    }
    __syncthreads();

    int w = tid >> 5, l = tid & 31;

    // QK^T: warp w owns rows w*8..w*8+7; lane owns cols l+32*jj
    u64 acc[8][4];
#pragma unroll
    for (int i = 0; i < 8; i++)
#pragma unroll
        for (int j = 0; j < 4; j++) acc[i][j] = 0ULL;
#pragma unroll 4
    for (int dp2 = 0; dp2 < 16; dp2++) {
        ulonglong2 kk[4];
#pragma unroll
        for (int jj = 0; jj < 4; jj++)
            kk[jj] = *(const ulonglong2*)&sm[KTO + (dp2*128 + l + 32*jj)*4];
#pragma unroll
        for (int rr = 0; rr < 8; rr++) {
            ulonglong2 qq = *(const ulonglong2*)&sm[QSO + (w*8 + rr)*64 + dp2*4];
#pragma unroll
            for (int jj = 0; jj < 4; jj++) {
                fma2(acc[rr][jj], qq.x, kk[jj].x);
                fma2(acc[rr][jj], qq.y, kk[jj].y);
            }
        }
    }
    __syncthreads();   // q/k tiles free; probs region becomes writable

    // mask + softmax per row; write probs in float4-quad layout; emit logsumexp
#pragma unroll
    for (int rr = 0; rr < 8; rr++) {
        int i = w*8 + rr;
        int qi = qidx[i];
        float dv[4];
#pragma unroll
        for (int jj = 0; jj < 4; jj++) {
            float2 a = unpack2(acc[rr][jj]);
            float t = a.x + a.y;
            dv[jj] = (qi != kidx[l + 32*jj]) ? t : -1e5f;
        }
        float m = fmaxf(fmaxf(dv[0], dv[1]), fmaxf(dv[2], dv[3]));
#pragma unroll
        for (int off = 16; off; off >>= 1) m = fmaxf(m, __shfl_xor_sync(0xffffffffu, m, off));
        float p[4], ssum = 0.f;
#pragma unroll
        for (int jj = 0; jj < 4; jj++) { p[jj] = expf(dv[jj] - m); ssum += p[jj]; }
#pragma unroll
        for (int off = 16; off; off >>= 1) ssum += __shfl_xor_sync(0xffffffffu, ssum, off);
        float inv = 1.f / ssum;
#pragma unroll
        for (int jj = 0; jj < 4; jj++) {
            int cq = l + 32*jj;                 // col 0..127
            sm[PBO + (cq >> 2)*PBQ + i*4 + (cq & 3)] = p[jj] * inv;
        }
        if (l == 0) g_lsort[(size_t)bh*(NHH*SS) + c*64 + i] = logf(ssum) + m;
    }
    __syncthreads();

    // PV: lane owns rows l and l+32; warp owns dims w*8..w*8+7; jq over 32 quads
    u64 o0[8], o1[8];
#pragma unroll
    for (int dd = 0; dd < 8; dd++) { o0[dd] = 0ULL; o1[dd] = 0ULL; }
#pragma unroll 4
    for (int jq = 0; jq < 32; jq++) {
        ulonglong2 pr0 = *(const ulonglong2*)&sm[PBO + jq*PBQ + l*4];
        ulonglong2 pr1 = *(const ulonglong2*)&sm[PBO + jq*PBQ + (l+32)*4];
#pragma unroll
        for (int dd = 0; dd < 8; dd++) {
            ulonglong2 vv = *(const ulonglong2*)&sm[VTO + (w*8 + dd)*128 + jq*4];
            fma2(o0[dd], pr0.x, vv.x);
            fma2(o0[dd], pr0.y, vv.y);
            fma2(o1[dd], pr1.x, vv.x);
            fma2(o1[dd], pr1.y, vv.y);
        }
    }
    __syncthreads();   // probs free; out-stage region writable
#pragma unroll
    for (int dd = 0; dd < 8; dd++) {
        float2 a = unpack2(o0[dd]); sm[OBO + l*OSTR + w*8 + dd] = a.x + a.y;
        float2 b2 = unpack2(o1[dd]); sm[OBO + (l+32)*OSTR + w*8 + dd] = b2.x + b2.y;
    }
    __syncthreads();
    {
        int r = tid >> 2, dq = (tid & 3) * 4;
        float* dst = g_osort + ((size_t)bh*(NHH*SS) + c*64 + r)*DD;
#pragma unroll
        for (int g = 0; g < 4; g++) {
            int d = dq + g*16;
            *(float4*)&dst[d] = *(const float4*)&sm[OBO + r*OSTR + d];
        }
    }
}

// ---------------- 5) key-side undo + combine rounds -------------------------
__global__ __launch_bounds__(256) void combine_kernel(float* __restrict__ out) {
    int row = blockIdx.x * 8 + (threadIdx.x >> 5);  // b*H*S rows
    int l = threadIdx.x & 31;
    int bh = row >> 12;
    int s = row & (SS - 1);
    int b = bh >> 3, h = bh & 7;
    float lg[NHH]; int up[NHH];
#pragma unroll
    for (int n = 0; n < NHH; n++) {
        int u = g_undo[((size_t)bh*NHH + n)*SS + s];
        up[n] = u;
        lg[n] = g_lsort[(size_t)bh*(NHH*SS) + n*SS + u];
    }
    float m = fmaxf(fmaxf(lg[0], lg[1]), fmaxf(lg[2], lg[3]));
    float w[NHH], wsum = 0.f;
#pragma unroll
    for (int n = 0; n < NHH; n++) { w[n] = expf(lg[n] - m); wsum += w[n]; }
    float inv = 1.f / wsum;
    float2 acc = make_float2(0.f, 0.f);
#pragma unroll
    for (int n = 0; n < NHH; n++) {
        float2 o = *(const float2*)&g_osort[((size_t)bh*(NHH*SS) + n*SS + up[n])*DD + l*2];
        acc.x += w[n]*o.x; acc.y += w[n]*o.y;
    }
    acc.x *= inv; acc.y *= inv;
    *(float2*)&out[((size_t)(b*SS + s))*(HH*DD) + h*DD + l*2] = acc;
}

// ---------------- launch -----------------------------------------------------
#define HASH_SMEM ((NHH*RSN + 64*VSS) * 4)

extern "C" void kernel_launch(void* const* d_in, const int* in_sizes, int n_in,
                              void* d_out, int out_size) {
    const float* dec = (const float*)d_in[0];
    const float* hid = (const float*)d_in[1];
    const float* wqk = (const float*)d_in[2];
    const float* wv  = (const float*)d_in[3];
    const float* rot = (const float*)d_in[4];
    float* out = (float*)d_out;

    cudaFuncSetAttribute(hash_kernel, cudaFuncAttributeMaxDynamicSharedMemorySize, HASH_SMEM);
    cudaFuncSetAttribute(attn_kernel, cudaFuncAttributeMaxDynamicSharedMemorySize, SMEMF*4);

    gemm_kernel<<<dim3(8, 64, 3), 256>>>(dec, hid, wqk, wv);
    hash_kernel<<<dim3(SS/64, HH, BB*2), 256, HASH_SMEM>>>(rot);
    sort_kernel<<<dim3(BB*HH*NHH, 2), 256>>>();
    attn_kernel<<<dim3(NCH, BB*HH), 256, SMEMF*4>>>();
    combine_kernel<<<BB*HH*SS/8, 256>>>(out);
}

// round 15
// speedup vs baseline: 1.0863x; 1.0355x over previous
#include <cuda_runtime.h>

typedef unsigned long long u64;

#define BB 2
#define HH 8
#define SS 4096
#define DD 64
#define HIDN 512
#define NHH 4
#define NCH 256
#define CHK 64

// ---------------- scratch (device globals; no allocations allowed) ----------
__device__ float g_q[BB*HH*SS*DD];
__device__ float g_k[BB*HH*SS*DD];
__device__ float g_v[BB*HH*SS*DD];
__device__ unsigned char g_bq[BB*HH*NHH*SS];
__device__ unsigned char g_bk[BB*HH*NHH*SS];
__device__ int g_sq[BB*HH*NHH*SS];
__device__ int g_sk[BB*HH*NHH*SS];
__device__ int g_undo[BB*HH*NHH*SS];
__device__ float g_osort[BB*HH*NHH*SS*DD];   // 64 MB
__device__ float g_lsort[BB*HH*NHH*SS];

// ---------------- packed f32x2 helpers --------------------------------------
__device__ __forceinline__ void fma2(u64 &d, u64 a, u64 b) {
    asm("fma.rn.f32x2 %0, %1, %2, %0;" : "+l"(d) : "l"(a), "l"(b));
}
__device__ __forceinline__ u64 pack2(float x, float y) {
    u64 r; asm("mov.b64 %0, {%1, %2};" : "=l"(r) : "f"(x), "f"(y)); return r;
}
__device__ __forceinline__ float2 unpack2(u64 a) {
    float x, y; asm("mov.b64 {%0, %1}, %2;" : "=f"(x), "=f"(y) : "l"(a));
    return make_float2(x, y);
}

// ---------------- shared GEMM body (128x64 tile, double-buffered) -----------
__device__ __forceinline__ void gemm_body(
        const float* __restrict__ X, const float* __restrict__ W,
        float* __restrict__ out, int m0, int n0,
        float (*As)[16][128], float (*Bs)[16][64], int tid) {
    int tx = tid & 15, ty = tid >> 4;
    int arow = tid >> 1, acol = (tid & 1) * 8;
    int brow = tid >> 4, bcol = (tid & 15) * 4;

    u64 acc[4][4];
#pragma unroll
    for (int i = 0; i < 4; i++)
#pragma unroll
        for (int j = 0; j < 4; j++) acc[i][j] = 0ULL;

    const float* Abase = X + (size_t)(m0 + arow) * HIDN + acol;
    const float* Bbase = W + (size_t)brow * HIDN + n0 + bcol;

    float4 ra0 = *(const float4*)(Abase);
    float4 ra1 = *(const float4*)(Abase + 4);
    float4 rb0 = *(const float4*)(Bbase);
    As[0][acol+0][arow]=ra0.x; As[0][acol+1][arow]=ra0.y; As[0][acol+2][arow]=ra0.z; As[0][acol+3][arow]=ra0.w;
    As[0][acol+4][arow]=ra1.x; As[0][acol+5][arow]=ra1.y; As[0][acol+6][arow]=ra1.z; As[0][acol+7][arow]=ra1.w;
    *(float4*)&Bs[0][brow][bcol] = rb0;
    ra0 = *(const float4*)(Abase + 16);
    ra1 = *(const float4*)(Abase + 20);
    rb0 = *(const float4*)(Bbase + (size_t)16 * HIDN);
    __syncthreads();

    int s = 0;
#pragma unroll 1
    for (int ch = 0; ch < HIDN/16; ch++, s ^= 1) {
        if (ch + 1 < HIDN/16) {
            int so = s ^ 1;
            As[so][acol+0][arow]=ra0.x; As[so][acol+1][arow]=ra0.y; As[so][acol+2][arow]=ra0.z; As[so][acol+3][arow]=ra0.w;
            As[so][acol+4][arow]=ra1.x; As[so][acol+5][arow]=ra1.y; As[so][acol+6][arow]=ra1.z; As[so][acol+7][arow]=ra1.w;
            *(float4*)&Bs[so][brow][bcol] = rb0;
        }
        if (ch + 2 < HIDN/16) {
            int k0 = (ch + 2) * 16;
            ra0 = *(const float4*)(Abase + k0);
            ra1 = *(const float4*)(Abase + k0 + 4);
            rb0 = *(const float4*)(Bbase + (size_t)k0 * HIDN);
        }
#pragma unroll
        for (int kk = 0; kk < 16; kk++) {
            u64 a2[4];
#pragma unroll
            for (int ii = 0; ii < 4; ii++) a2[ii] = *(const u64*)&As[s][kk][ty*8 + 2*ii];
            float4 bv = *(const float4*)&Bs[s][kk][tx*4];
            u64 b2[4] = { pack2(bv.x,bv.x), pack2(bv.y,bv.y), pack2(bv.z,bv.z), pack2(bv.w,bv.w) };
#pragma unroll
            for (int ii = 0; ii < 4; ii++)
#pragma unroll
                for (int j = 0; j < 4; j++) fma2(acc[ii][j], a2[ii], b2[j]);
        }
        __syncthreads();
    }
    int h = n0 >> 6;
#pragma unroll
    for (int ii = 0; ii < 4; ii++) {
        float2 c0 = unpack2(acc[ii][0]), c1 = unpack2(acc[ii][1]);
        float2 c2 = unpack2(acc[ii][2]), c3 = unpack2(acc[ii][3]);
        int m = m0 + ty*8 + 2*ii;
        int b = m >> 12, sx = m & (SS - 1);
        float* o0 = out + ((size_t)(b*HH + h)*SS + sx)*DD + tx*4;
        *(float4*)o0 = make_float4(c0.x, c1.x, c2.x, c3.x);
        int m1 = m + 1; int b1 = m1 >> 12, s1 = m1 & (SS - 1);
        float* o1 = out + ((size_t)(b1*HH + h)*SS + s1)*DD + tx*4;
        *(float4*)o1 = make_float4(c0.y, c1.y, c2.y, c3.y);
    }
}

// ---------------- 1) Q,K GEMMs ------------------------------------------------
__global__ __launch_bounds__(256) void gemm_kernel(
        const float* __restrict__ dec, const float* __restrict__ hid,
        const float* __restrict__ wqk) {
    __shared__ float As[2][16][128];
    __shared__ float Bs[2][16][64];
    int z = blockIdx.z;
    const float* X = (z == 0) ? dec : hid;
    float* out = (z == 0) ? g_q : g_k;
    gemm_body(X, wqk, out, blockIdx.y * 128, blockIdx.x * 64, As, Bs, threadIdx.x);
}

// ---------------- 2) fused: V GEMM (blocks 0..511) + LSH hash (512..2559) ---
#define RSN 4104          // n-stride in floats
#define VSS 65            // v tile token stride
#define HASH_SMEM ((NHH*RSN + 64*VSS) * 4)

__global__ __launch_bounds__(256) void hash_gemmv_kernel(
        const float* __restrict__ hid, const float* __restrict__ wv,
        const float* __restrict__ rot) {
    extern __shared__ float sh[];
    int tid = threadIdx.x;

    if (blockIdx.x < 512) {
        // ---- V GEMM role (dynamic smem aliased) ----
        float (*As)[16][128] = (float(*)[16][128])sh;
        float (*Bs)[16][64]  = (float(*)[16][64])(sh + 2*16*128);
        int bx = blockIdx.x;
        gemm_body(hid, wv, g_v, (bx >> 3) * 128, (bx & 7) * 64, As, Bs, tid);
        return;
    }

    // ---- hash role ----
    int idx = blockIdx.x - 512;
    int tokblk = idx & 63;
    int h = (idx >> 6) & 7;
    int bz = idx >> 9;                 // 0..3
    int b = bz >> 1, tensor = bz & 1;

    float* rs = sh;                 // rs[n*RSN + d*64 + r]
    float* vs = sh + NHH*RSN;       // vs[tok*VSS + d]

    const float* rsrc = rot + (size_t)h * (64*NHH*64);
    for (int i2 = tid; i2 < NHH*64*64; i2 += 256) {
        int r = i2 & 63; int dn = i2 >> 6;   // dn = d*NHH + n
        int n = dn & 3, d = dn >> 2;
        rs[n*RSN + d*64 + r] = rsrc[i2];
    }
    int tok0 = tokblk * 64;
    const float* vbase = (tensor == 0 ? g_q : g_k) + ((size_t)(b*HH + h)*SS + tok0)*DD;
    for (int i2 = tid; i2 < 64*(DD/4); i2 += 256) {
        int tok = i2 >> 4, d4 = (i2 & 15) * 4;
        float4 t4 = *(const float4*)(vbase + tok*DD + d4);
        vs[tok*VSS + d4 + 0] = t4.x; vs[tok*VSS + d4 + 1] = t4.y;
        vs[tok*VSS + d4 + 2] = t4.z; vs[tok*VSS + d4 + 3] = t4.w;
    }
    __syncthreads();

    int tq = tid >> 4, tr = tid & 15;
    int n = tr >> 2, rg = tr & 3;
    const float* rbase = rs + n*RSN + rg*16;

    u64 acc[4][8];
#pragma unroll
    for (int i = 0; i < 4; i++)
#pragma unroll
        for (int j = 0; j < 8; j++) acc[i][j] = 0ULL;

    for (int d = 0; d < 64; d++) {
        u64 b2[8];
        const u64* rp = (const u64*)(rbase + d*64);
#pragma unroll
        for (int j = 0; j < 8; j++) b2[j] = rp[j];
#pragma unroll
        for (int i = 0; i < 4; i++) {
            float vv = vs[(tq*4 + i)*VSS + d];
            u64 a2 = pack2(vv, vv);
#pragma unroll
            for (int j = 0; j < 8; j++) fma2(acc[i][j], a2, b2[j]);
        }
    }

    unsigned char* outb = (tensor == 0 ? g_bq : g_bk);
#pragma unroll
    for (int i = 0; i < 4; i++) {
        float bpv = -1e30f, bnv = -1e30f; int bpi = 0, bni = 0;
#pragma unroll
        for (int j = 0; j < 8; j++) {
            float2 a = unpack2(acc[i][j]);
            int r0 = rg*16 + 2*j;
            if (a.x > bpv)  { bpv = a.x;  bpi = r0; }
            if (a.y > bpv)  { bpv = a.y;  bpi = r0 + 1; }
            if (-a.x > bnv) { bnv = -a.x; bni = r0; }
            if (-a.y > bnv) { bnv = -a.y; bni = r0 + 1; }
        }
#pragma unroll
        for (int off = 1; off < 4; off <<= 1) {
            float ov = __shfl_down_sync(0xffffffffu, bpv, off);
            int   oi = __shfl_down_sync(0xffffffffu, bpi, off);
            if (ov > bpv) { bpv = ov; bpi = oi; }
            float on = __shfl_down_sync(0xffffffffu, bnv, off);
            int   oj = __shfl_down_sync(0xffffffffu, bni, off);
            if (on > bnv) { bnv = on; bni = oj; }
        }
        if (rg == 0) {
            int bucket = (bpv >= bnv) ? bpi : 64 + bni;  // pos side wins ties
            outb[((size_t)(b*HH + h)*NHH + n)*SS + tok0 + tq*4 + i] = (unsigned char)bucket;
        }
    }
}

// ---------------- 3) warp-parallel stable counting sort ---------------------
__global__ __launch_bounds__(256) void sort_kernel() {
    __shared__ unsigned char sb[SS];
    __shared__ int wcnt[8][128];
    __shared__ int woff[8][128];
    __shared__ int tot[128];
    int combo = blockIdx.x;
    int tensor = blockIdx.y;
    const unsigned char* bg = (tensor == 0 ? g_bq : g_bk) + (size_t)combo * SS;
    int t = threadIdx.x, w = t >> 5, l = t & 31;
    for (int i = t; i < SS/4; i += 256)
        ((unsigned int*)sb)[i] = ((const unsigned int*)bg)[i];
    if (t < 128) {
#pragma unroll
        for (int ww = 0; ww < 8; ww++) wcnt[ww][t] = 0;
    }
    __syncthreads();
    int seg = w * 512;
    int myb[16];
#pragma unroll
    for (int it = 0; it < 16; it++) {
        int bkt = sb[seg + it*32 + l];
        myb[it] = bkt;
        unsigned mask = __match_any_sync(0xffffffffu, (unsigned)bkt);
        if ((__ffs(mask) - 1) == l) wcnt[w][bkt] += __popc(mask);
    }
    __syncthreads();
    if (t < 128) {
        int s = 0;
#pragma unroll
        for (int ww = 0; ww < 8; ww++) s += wcnt[ww][t];
        tot[t] = s;
    }
    __syncthreads();
    if (t == 0) {
        int a = 0;
        for (int bkt = 0; bkt < 128; bkt++) { int c = tot[bkt]; tot[bkt] = a; a += c; }
    }
    __syncthreads();
    if (t < 128) {
        int run = tot[t];
#pragma unroll
        for (int ww = 0; ww < 8; ww++) { int c = wcnt[ww][t]; woff[ww][t] = run; run += c; }
    }
    __syncthreads();
    int* sorted = (tensor == 0 ? g_sq : g_sk) + (size_t)combo * SS;
    int* undo = g_undo + (size_t)combo * SS;
#pragma unroll
    for (int it = 0; it < 16; it++) {
        int p = seg + it*32 + l;
        int bkt = myb[it];
        unsigned mask = __match_any_sync(0xffffffffu, (unsigned)bkt);
        int leader = __ffs(mask) - 1;
        int rank = __popc(mask & ((1u << l) - 1u));
        int base = 0;
        if (l == leader) { base = woff[w][bkt]; woff[w][bkt] = base + __popc(mask); }
        base = __shfl_sync(mask, base, leader);
        sorted[base + rank] = p;
        if (tensor == 1) undo[p] = base + rank;
    }
}

// ---------------- 4) chunk attention (R12 layouts/loader) -------------------
#define QSO 0
#define KTO 4096
#define VTO 12288
#define PBO 0
#define PBQ 260
#define OBO 0
#define OSTR 68
#define IDXO 20480
#define SMEMF 20672

__global__ __launch_bounds__(256, 2) void attn_kernel() {
    extern __shared__ float sm[];
    int tid = threadIdx.x;
    int c = blockIdx.x;          // global chunk 0..255 (ring across rounds)
    int bh = blockIdx.y;         // b*H + h
    int n = c >> 6, cl = c & 63;
    int cp = (c + NCH - 1) & (NCH - 1);
    int np = cp >> 6, clp = cp & 63;

    const int* sq_n = g_sq + ((size_t)bh*NHH + n)*SS + cl*64;
    const int* sq_p = g_sq + ((size_t)bh*NHH + np)*SS + clp*64;
    const int* sk_n = g_sk + ((size_t)bh*NHH + n)*SS + cl*64;
    const int* sk_p = g_sk + ((size_t)bh*NHH + np)*SS + clp*64;

    int* qidx = (int*)&sm[IDXO];
    int* kidx = qidx + 64;
    if (tid < 64)       { int s = sq_n[tid]; qidx[tid] = s; kidx[64 + tid] = s; }
    else if (tid < 128) { kidx[tid - 64] = sq_p[tid - 64]; }

    // q tile [64 x 64]
    {
        int r = tid >> 2, dq = (tid & 3) * 4;
        const float* src = g_q + ((size_t)bh*SS + sq_n[r])*DD;
#pragma unroll
        for (int g = 0; g < 4; g++) {
            int d = dq + g*16;
            *(float4*)&sm[QSO + r*64 + d] = *(const float4*)&src[d];
        }
    }
    // K (normalize, dim-major float4 tiles) by threads 0..127; V^T by 128..255
    if (tid < 128) {
        int j = tid;
        int s = (j < 64) ? sk_p[j] : sk_n[j - 64];
        const float4* ksrc = (const float4*)(g_k + ((size_t)bh*SS + s)*DD);
        float ssq = 0.f;
#pragma unroll
        for (int g = 0; g < 16; g++) {
            float4 t = ksrc[g];
            ssq += t.x*t.x + t.y*t.y + t.z*t.z + t.w*t.w;
        }
        float sc = rsqrtf(ssq * (1.0f/64.0f) + 1e-6f) * 0.125f;
#pragma unroll
        for (int g = 0; g < 16; g++) {
            float4 t = ksrc[g];
            *(float4*)&sm[KTO + (g*128 + j)*4] = make_float4(t.x*sc, t.y*sc, t.z*sc, t.w*sc);
        }
    } else {
        int j = tid - 128;
        int s = (j < 64) ? sk_p[j] : sk_n[j - 64];
        const float4* vsrc = (const float4*)(g_v + ((size_t)bh*SS + s)*DD);
#pragma unroll
        for (int g = 0; g < 16; g++) {
            float4 t = vsrc[g];
            sm[VTO + (4*g+0)*128 + j] = t.x;
            sm[VTO + (4*g+1)*128 + j] = t.y;
            sm[VTO + (4*g+2)*128 + j] = t.z;
            sm[VTO + (4*g+3)*128 + j] = t.w;
        }
    }
    __syncthreads();

    int w = tid >> 5, l = tid & 31;

    // QK^T: warp w owns rows w*8..w*8+7; lane owns cols l+32*jj
    u64 acc[8][4];
#pragma unroll
    for (int i = 0; i < 8; i++)
#pragma unroll
        for (int j = 0; j < 4; j++) acc[i][j] = 0ULL;
#pragma unroll 4
    for (int dp2 = 0; dp2 < 16; dp2++) {
        ulonglong2 kk[4];
#pragma unroll
        for (int jj = 0; jj < 4; jj++)
            kk[jj] = *(const ulonglong2*)&sm[KTO + (dp2*128 + l + 32*jj)*4];
#pragma unroll
        for (int rr = 0; rr < 8; rr++) {
            ulonglong2 qq = *(const ulonglong2*)&sm[QSO + (w*8 + rr)*64 + dp2*4];
#pragma unroll
            for (int jj = 0; jj < 4; jj++) {
                fma2(acc[rr][jj], qq.x, kk[jj].x);
                fma2(acc[rr][jj], qq.y, kk[jj].y);
            }
        }
    }
    __syncthreads();   // q/k tiles free; probs region becomes writable

    // mask + softmax per row; write probs in float4-quad layout; emit logsumexp
#pragma unroll
    for (int rr = 0; rr < 8; rr++) {
        int i = w*8 + rr;
        int qi = qidx[i];
        float dv[4];
#pragma unroll
        for (int jj = 0; jj < 4; jj++) {
            float2 a = unpack2(acc[rr][jj]);
            float t = a.x + a.y;
            dv[jj] = (qi != kidx[l + 32*jj]) ? t : -1e5f;
        }
        float m = fmaxf(fmaxf(dv[0], dv[1]), fmaxf(dv[2], dv[3]));
#pragma unroll
        for (int off = 16; off; off >>= 1) m = fmaxf(m, __shfl_xor_sync(0xffffffffu, m, off));
        float p[4], ssum = 0.f;
#pragma unroll
        for (int jj = 0; jj < 4; jj++) { p[jj] = expf(dv[jj] - m); ssum += p[jj]; }
#pragma unroll
        for (int off = 16; off; off >>= 1) ssum += __shfl_xor_sync(0xffffffffu, ssum, off);
        float inv = 1.f / ssum;
#pragma unroll
        for (int jj = 0; jj < 4; jj++) {
            int cq = l + 32*jj;                 // col 0..127
            sm[PBO + (cq >> 2)*PBQ + i*4 + (cq & 3)] = p[jj] * inv;
        }
        if (l == 0) g_lsort[(size_t)bh*(NHH*SS) + c*64 + i] = logf(ssum) + m;
    }
    __syncthreads();

    // PV: lane owns rows l and l+32; warp owns dims w*8..w*8+7; jq over 32 quads
    u64 o0[8], o1[8];
#pragma unroll
    for (int dd = 0; dd < 8; dd++) { o0[dd] = 0ULL; o1[dd] = 0ULL; }
#pragma unroll 4
    for (int jq = 0; jq < 32; jq++) {
        ulonglong2 pr0 = *(const ulonglong2*)&sm[PBO + jq*PBQ + l*4];
        ulonglong2 pr1 = *(const ulonglong2*)&sm[PBO + jq*PBQ + (l+32)*4];
#pragma unroll
        for (int dd = 0; dd < 8; dd++) {
            ulonglong2 vv = *(const ulonglong2*)&sm[VTO + (w*8 + dd)*128 + jq*4];
            fma2(o0[dd], pr0.x, vv.x);
            fma2(o0[dd], pr0.y, vv.y);
            fma2(o1[dd], pr1.x, vv.x);
            fma2(o1[dd], pr1.y, vv.y);
        }
    }
    __syncthreads();   // probs free; out-stage region writable
#pragma unroll
    for (int dd = 0; dd < 8; dd++) {
        float2 a = unpack2(o0[dd]); sm[OBO + l*OSTR + w*8 + dd] = a.x + a.y;
        float2 b2 = unpack2(o1[dd]); sm[OBO + (l+32)*OSTR + w*8 + dd] = b2.x + b2.y;
    }
    __syncthreads();
    {
        int r = tid >> 2, dq = (tid & 3) * 4;
        float* dst = g_osort + ((size_t)bh*(NHH*SS) + c*64 + r)*DD;
#pragma unroll
        for (int g = 0; g < 4; g++) {
            int d = dq + g*16;
            *(float4*)&dst[d] = *(const float4*)&sm[OBO + r*OSTR + d];
        }
    }
}

// ---------------- 5) key-side undo + combine rounds -------------------------
__global__ __launch_bounds__(256) void combine_kernel(float* __restrict__ out) {
    int row = blockIdx.x * 8 + (threadIdx.x >> 5);  // b*H*S rows
    int l = threadIdx.x & 31;
    int bh = row >> 12;
    int s = row & (SS - 1);
    int b = bh >> 3, h = bh & 7;
    float lg[NHH]; int up[NHH];
#pragma unroll
    for (int n = 0; n < NHH; n++) {
        int u = g_undo[((size_t)bh*NHH + n)*SS + s];
        up[n] = u;
        lg[n] = g_lsort[(size_t)bh*(NHH*SS) + n*SS + u];
    }
    float m = fmaxf(fmaxf(lg[0], lg[1]), fmaxf(lg[2], lg[3]));
    float w[NHH], wsum = 0.f;
#pragma unroll
    for (int n = 0; n < NHH; n++) { w[n] = expf(lg[n] - m); wsum += w[n]; }
    float inv = 1.f / wsum;
    float2 acc = make_float2(0.f, 0.f);
#pragma unroll
    for (int n = 0; n < NHH; n++) {
        float2 o = *(const float2*)&g_osort[((size_t)bh*(NHH*SS) + n*SS + up[n])*DD + l*2];
        acc.x += w[n]*o.x; acc.y += w[n]*o.y;
    }
    acc.x *= inv; acc.y *= inv;
    *(float2*)&out[((size_t)(b*SS + s))*(HH*DD) + h*DD + l*2] = acc;
}

// ---------------- launch -----------------------------------------------------
extern "C" void kernel_launch(void* const* d_in, const int* in_sizes, int n_in,
                              void* d_out, int out_size) {
    const float* dec = (const float*)d_in[0];
    const float* hid = (const float*)d_in[1];
    const float* wqk = (const float*)d_in[2];
    const float* wv  = (const float*)d_in[3];
    const float* rot = (const float*)d_in[4];
    float* out = (float*)d_out;

    cudaFuncSetAttribute(hash_gemmv_kernel, cudaFuncAttributeMaxDynamicSharedMemorySize, HASH_SMEM);
    cudaFuncSetAttribute(attn_kernel, cudaFuncAttributeMaxDynamicSharedMemorySize, SMEMF*4);

    gemm_kernel<<<dim3(8, 64, 2), 256>>>(dec, hid, wqk);       // Q, K
    hash_gemmv_kernel<<<2560, 256, HASH_SMEM>>>(hid, wv, rot); // V GEMM + hash
    sort_kernel<<<dim3(BB*HH*NHH, 2), 256>>>();
    attn_kernel<<<dim3(NCH, BB*HH), 256, SMEMF*4>>>();
    combine_kernel<<<BB*HH*SS/8, 256>>>(out);
}

// round 16
// speedup vs baseline: 1.0939x; 1.0070x over previous
#include <cuda_runtime.h>

typedef unsigned long long u64;

#define BB 2
#define HH 8
#define SS 4096
#define DD 64
#define HIDN 512
#define NHH 4
#define NCH 256
#define CHK 64

// ---------------- scratch (device globals; no allocations allowed) ----------
__device__ float g_q[BB*HH*SS*DD];
__device__ float g_k[BB*HH*SS*DD];
__device__ float g_v[BB*HH*SS*DD];
__device__ unsigned char g_bq[BB*HH*NHH*SS];
__device__ unsigned char g_bk[BB*HH*NHH*SS];
__device__ int g_sq[BB*HH*NHH*SS];
__device__ int g_sk[BB*HH*NHH*SS];
__device__ int g_undo[BB*HH*NHH*SS];
__device__ float g_osort[BB*HH*NHH*SS*DD];   // 64 MB
__device__ float g_lsort[BB*HH*NHH*SS];

// ---------------- packed f32x2 helpers --------------------------------------
__device__ __forceinline__ void fma2(u64 &d, u64 a, u64 b) {
    asm("fma.rn.f32x2 %0, %1, %2, %0;" : "+l"(d) : "l"(a), "l"(b));
}
__device__ __forceinline__ u64 pack2(float x, float y) {
    u64 r; asm("mov.b64 %0, {%1, %2};" : "=l"(r) : "f"(x), "f"(y)); return r;
}
__device__ __forceinline__ float2 unpack2(u64 a) {
    float x, y; asm("mov.b64 {%0, %1}, %2;" : "=f"(x), "=f"(y) : "l"(a));
    return make_float2(x, y);
}

// ---------------- shared GEMM body (128x64 tile, double-buffered) -----------
__device__ __forceinline__ void gemm_body(
        const float* __restrict__ X, const float* __restrict__ W,
        float* __restrict__ out, int m0, int n0,
        float (*As)[16][128], float (*Bs)[16][64], int tid) {
    int tx = tid & 15, ty = tid >> 4;
    int arow = tid >> 1, acol = (tid & 1) * 8;
    int brow = tid >> 4, bcol = (tid & 15) * 4;

    u64 acc[4][4];
#pragma unroll
    for (int i = 0; i < 4; i++)
#pragma unroll
        for (int j = 0; j < 4; j++) acc[i][j] = 0ULL;

    const float* Abase = X + (size_t)(m0 + arow) * HIDN + acol;
    const float* Bbase = W + (size_t)brow * HIDN + n0 + bcol;

    float4 ra0 = *(const float4*)(Abase);
    float4 ra1 = *(const float4*)(Abase + 4);
    float4 rb0 = *(const float4*)(Bbase);
    As[0][acol+0][arow]=ra0.x; As[0][acol+1][arow]=ra0.y; As[0][acol+2][arow]=ra0.z; As[0][acol+3][arow]=ra0.w;
    As[0][acol+4][arow]=ra1.x; As[0][acol+5][arow]=ra1.y; As[0][acol+6][arow]=ra1.z; As[0][acol+7][arow]=ra1.w;
    *(float4*)&Bs[0][brow][bcol] = rb0;
    ra0 = *(const float4*)(Abase + 16);
    ra1 = *(const float4*)(Abase + 20);
    rb0 = *(const float4*)(Bbase + (size_t)16 * HIDN);
    __syncthreads();

    int s = 0;
#pragma unroll 1
    for (int ch = 0; ch < HIDN/16; ch++, s ^= 1) {
        if (ch + 1 < HIDN/16) {
            int so = s ^ 1;
            As[so][acol+0][arow]=ra0.x; As[so][acol+1][arow]=ra0.y; As[so][acol+2][arow]=ra0.z; As[so][acol+3][arow]=ra0.w;
            As[so][acol+4][arow]=ra1.x; As[so][acol+5][arow]=ra1.y; As[so][acol+6][arow]=ra1.z; As[so][acol+7][arow]=ra1.w;
            *(float4*)&Bs[so][brow][bcol] = rb0;
        }
        if (ch + 2 < HIDN/16) {
            int k0 = (ch + 2) * 16;
            ra0 = *(const float4*)(Abase + k0);
            ra1 = *(const float4*)(Abase + k0 + 4);
            rb0 = *(const float4*)(Bbase + (size_t)k0 * HIDN);
        }
#pragma unroll
        for (int kk = 0; kk < 16; kk++) {
            ulonglong2 a01 = *(const ulonglong2*)&As[s][kk][ty*8];
            ulonglong2 a23 = *(const ulonglong2*)&As[s][kk][ty*8 + 4];
            u64 a2[4] = { a01.x, a01.y, a23.x, a23.y };
            float4 bv = *(const float4*)&Bs[s][kk][tx*4];
            u64 b2[4] = { pack2(bv.x,bv.x), pack2(bv.y,bv.y), pack2(bv.z,bv.z), pack2(bv.w,bv.w) };
#pragma unroll
            for (int ii = 0; ii < 4; ii++)
#pragma unroll
                for (int j = 0; j < 4; j++) fma2(acc[ii][j], a2[ii], b2[j]);
        }
        __syncthreads();
    }
    int h = n0 >> 6;
#pragma unroll
    for (int ii = 0; ii < 4; ii++) {
        float2 c0 = unpack2(acc[ii][0]), c1 = unpack2(acc[ii][1]);
        float2 c2 = unpack2(acc[ii][2]), c3 = unpack2(acc[ii][3]);
        int m = m0 + ty*8 + 2*ii;
        int b = m >> 12, sx = m & (SS - 1);
        float* o0 = out + ((size_t)(b*HH + h)*SS + sx)*DD + tx*4;
        *(float4*)o0 = make_float4(c0.x, c1.x, c2.x, c3.x);
        int m1 = m + 1; int b1 = m1 >> 12, s1 = m1 & (SS - 1);
        float* o1 = out + ((size_t)(b1*HH + h)*SS + s1)*DD + tx*4;
        *(float4*)o1 = make_float4(c0.y, c1.y, c2.y, c3.y);
    }
}

// ---------------- 1) Q,K GEMMs ------------------------------------------------
__global__ __launch_bounds__(256) void gemm_kernel(
        const float* __restrict__ dec, const float* __restrict__ hid,
        const float* __restrict__ wqk) {
    __shared__ __align__(16) float As[2][16][128];
    __shared__ __align__(16) float Bs[2][16][64];
    int z = blockIdx.z;
    const float* X = (z == 0) ? dec : hid;
    float* out = (z == 0) ? g_q : g_k;
    gemm_body(X, wqk, out, blockIdx.y * 128, blockIdx.x * 64, As, Bs, threadIdx.x);
}

// ---------------- 2) fused: V GEMM (blocks 0..511) + LSH hash (512..2559) ---
#define RSN 4104          // n-stride in floats
#define VDS 68            // v tile d-stride (transposed [d][tok])
#define HASH_SMEM ((NHH*RSN + 64*VDS) * 4)

__global__ __launch_bounds__(256) void hash_gemmv_kernel(
        const float* __restrict__ hid, const float* __restrict__ wv,
        const float* __restrict__ rot) {
    extern __shared__ __align__(16) float sh[];
    int tid = threadIdx.x;

    if (blockIdx.x < 512) {
        // ---- V GEMM role (dynamic smem aliased) ----
        float (*As)[16][128] = (float(*)[16][128])sh;
        float (*Bs)[16][64]  = (float(*)[16][64])(sh + 2*16*128);
        int bx = blockIdx.x;
        gemm_body(hid, wv, g_v, (bx >> 3) * 128, (bx & 7) * 64, As, Bs, tid);
        return;
    }

    // ---- hash role ----
    int idx = blockIdx.x - 512;
    int tokblk = idx & 63;
    int h = (idx >> 6) & 7;
    int bz = idx >> 9;                 // 0..3
    int b = bz >> 1, tensor = bz & 1;

    float* rs = sh;                 // rs[n*RSN + d*64 + r]
    float* vs = sh + NHH*RSN;       // vs[d*VDS + tok]   (transposed)

    const float* rsrc = rot + (size_t)h * (64*NHH*64);
    for (int i2 = tid; i2 < NHH*64*64; i2 += 256) {
        int r = i2 & 63; int dn = i2 >> 6;   // dn = d*NHH + n
        int n = dn & 3, d = dn >> 2;
        rs[n*RSN + d*64 + r] = rsrc[i2];
    }
    int tok0 = tokblk * 64;
    const float* vbase = (tensor == 0 ? g_q : g_k) + ((size_t)(b*HH + h)*SS + tok0)*DD;
    for (int i2 = tid; i2 < 64*(DD/4); i2 += 256) {
        int tok = i2 >> 4, d4 = (i2 & 15) * 4;
        float4 t4 = *(const float4*)(vbase + tok*DD + d4);
        vs[(d4+0)*VDS + tok] = t4.x; vs[(d4+1)*VDS + tok] = t4.y;
        vs[(d4+2)*VDS + tok] = t4.z; vs[(d4+3)*VDS + tok] = t4.w;
    }
    __syncthreads();

    int tq = tid >> 4, tr = tid & 15;
    int n = tr >> 2, rg = tr & 3;
    const float* rbase = rs + n*RSN + rg*16;

    u64 acc[4][8];
#pragma unroll
    for (int i = 0; i < 4; i++)
#pragma unroll
        for (int j = 0; j < 8; j++) acc[i][j] = 0ULL;

    for (int d = 0; d < 64; d++) {
        ulonglong2 r01 = *(const ulonglong2*)(rbase + d*64);
        ulonglong2 r23 = *(const ulonglong2*)(rbase + d*64 + 4);
        ulonglong2 r45 = *(const ulonglong2*)(rbase + d*64 + 8);
        ulonglong2 r67 = *(const ulonglong2*)(rbase + d*64 + 12);
        u64 b2[8] = { r01.x, r01.y, r23.x, r23.y, r45.x, r45.y, r67.x, r67.y };
        float4 vv4 = *(const float4*)(vs + d*VDS + tq*4);
        u64 a2[4] = { pack2(vv4.x,vv4.x), pack2(vv4.y,vv4.y),
                      pack2(vv4.z,vv4.z), pack2(vv4.w,vv4.w) };
#pragma unroll
        for (int i = 0; i < 4; i++)
#pragma unroll
            for (int j = 0; j < 8; j++) fma2(acc[i][j], a2[i], b2[j]);
    }

    unsigned char* outb = (tensor == 0 ? g_bq : g_bk);
#pragma unroll
    for (int i = 0; i < 4; i++) {
        float bpv = -1e30f, bnv = -1e30f; int bpi = 0, bni = 0;
#pragma unroll
        for (int j = 0; j < 8; j++) {
            float2 a = unpack2(acc[i][j]);
            int r0 = rg*16 + 2*j;
            if (a.x > bpv)  { bpv = a.x;  bpi = r0; }
            if (a.y > bpv)  { bpv = a.y;  bpi = r0 + 1; }
            if (-a.x > bnv) { bnv = -a.x; bni = r0; }
            if (-a.y > bnv) { bnv = -a.y; bni = r0 + 1; }
        }
#pragma unroll
        for (int off = 1; off < 4; off <<= 1) {
            float ov = __shfl_down_sync(0xffffffffu, bpv, off);
            int   oi = __shfl_down_sync(0xffffffffu, bpi, off);
            if (ov > bpv) { bpv = ov; bpi = oi; }
            float on = __shfl_down_sync(0xffffffffu, bnv, off);
            int   oj = __shfl_down_sync(0xffffffffu, bni, off);
            if (on > bnv) { bnv = on; bni = oj; }
        }
        if (rg == 0) {
            int bucket = (bpv >= bnv) ? bpi : 64 + bni;  // pos side wins ties
            outb[((size_t)(b*HH + h)*NHH + n)*SS + tok0 + tq*4 + i] = (unsigned char)bucket;
        }
    }
}

// ---------------- 3) warp-parallel stable counting sort ---------------------
__global__ __launch_bounds__(256) void sort_kernel() {
    __shared__ unsigned char sb[SS];
    __shared__ int wcnt[8][128];
    __shared__ int woff[8][128];
    __shared__ int tot[128];
    int combo = blockIdx.x;
    int tensor = blockIdx.y;
    const unsigned char* bg = (tensor == 0 ? g_bq : g_bk) + (size_t)combo * SS;
    int t = threadIdx.x, w = t >> 5, l = t & 31;
    for (int i = t; i < SS/4; i += 256)
        ((unsigned int*)sb)[i] = ((const unsigned int*)bg)[i];
    if (t < 128) {
#pragma unroll
        for (int ww = 0; ww < 8; ww++) wcnt[ww][t] = 0;
    }
    __syncthreads();
    int seg = w * 512;
    int myb[16];
#pragma unroll
    for (int it = 0; it < 16; it++) {
        int bkt = sb[seg + it*32 + l];
        myb[it] = bkt;
        unsigned mask = __match_any_sync(0xffffffffu, (unsigned)bkt);
        if ((__ffs(mask) - 1) == l) wcnt[w][bkt] += __popc(mask);
    }
    __syncthreads();
    if (t < 128) {
        int s = 0;
#pragma unroll
        for (int ww = 0; ww < 8; ww++) s += wcnt[ww][t];
        tot[t] = s;
    }
    __syncthreads();
    if (t == 0) {
        int a = 0;
        for (int bkt = 0; bkt < 128; bkt++) { int c = tot[bkt]; tot[bkt] = a; a += c; }
    }
    __syncthreads();
    if (t < 128) {
        int run = tot[t];
#pragma unroll
        for (int ww = 0; ww < 8; ww++) { int c = wcnt[ww][t]; woff[ww][t] = run; run += c; }
    }
    __syncthreads();
    int* sorted = (tensor == 0 ? g_sq : g_sk) + (size_t)combo * SS;
    int* undo = g_undo + (size_t)combo * SS;
#pragma unroll
    for (int it = 0; it < 16; it++) {
        int p = seg + it*32 + l;
        int bkt = myb[it];
        unsigned mask = __match_any_sync(0xffffffffu, (unsigned)bkt);
        int leader = __ffs(mask) - 1;
        int rank = __popc(mask & ((1u << l) - 1u));
        int base = 0;
        if (l == leader) { base = woff[w][bkt]; woff[w][bkt] = base + __popc(mask); }
        base = __shfl_sync(mask, base, leader);
        sorted[base + rank] = p;
        if (tensor == 1) undo[p] = base + rank;
    }
}

// ---------------- 4) chunk attention (direct output store) ------------------
#define QSO 0
#define KTO 4096
#define VTO 12288
#define PBO 0
#define PBQ 260
#define IDXO 20480
#define SMEMF 20672

__global__ __launch_bounds__(256, 2) void attn_kernel() {
    extern __shared__ float sm[];
    int tid = threadIdx.x;
    int c = blockIdx.x;          // global chunk 0..255 (ring across rounds)
    int bh = blockIdx.y;         // b*H + h
    int n = c >> 6, cl = c & 63;
    int cp = (c + NCH - 1) & (NCH - 1);
    int np = cp >> 6, clp = cp & 63;

    const int* sq_n = g_sq + ((size_t)bh*NHH + n)*SS + cl*64;
    const int* sq_p = g_sq + ((size_t)bh*NHH + np)*SS + clp*64;
    const int* sk_n = g_sk + ((size_t)bh*NHH + n)*SS + cl*64;
    const int* sk_p = g_sk + ((size_t)bh*NHH + np)*SS + clp*64;

    int* qidx = (int*)&sm[IDXO];
    int* kidx = qidx + 64;
    if (tid < 64)       { int s = sq_n[tid]; qidx[tid] = s; kidx[64 + tid] = s; }
    else if (tid < 128) { kidx[tid - 64] = sq_p[tid - 64]; }

    // q tile [64 x 64]
    {
        int r = tid >> 2, dq = (tid & 3) * 4;
        const float* src = g_q + ((size_t)bh*SS + sq_n[r])*DD;
#pragma unroll
        for (int g = 0; g < 4; g++) {
            int d = dq + g*16;
            *(float4*)&sm[QSO + r*64 + d] = *(const float4*)&src[d];
        }
    }
    // K (normalize, dim-major float4 tiles) by threads 0..127; V^T by 128..255
    if (tid < 128) {
        int j = tid;
        int s = (j < 64) ? sk_p[j] : sk_n[j - 64];
        const float4* ksrc = (const float4*)(g_k + ((size_t)bh*SS + s)*DD);
        float ssq = 0.f;
#pragma unroll
        for (int g = 0; g < 16; g++) {
            float4 t = ksrc[g];
            ssq += t.x*t.x + t.y*t.y + t.z*t.z + t.w*t.w;
        }
        float sc = rsqrtf(ssq * (1.0f/64.0f) + 1e-6f) * 0.125f;
#pragma unroll
        for (int g = 0; g < 16; g++) {
            float4 t = ksrc[g];
            *(float4*)&sm[KTO + (g*128 + j)*4] = make_float4(t.x*sc, t.y*sc, t.z*sc, t.w*sc);
        }
    } else {
        int j = tid - 128;
        int s = (j < 64) ? sk_p[j] : sk_n[j - 64];
        const float4* vsrc = (const float4*)(g_v + ((size_t)bh*SS + s)*DD);
#pragma unroll
        for (int g = 0; g < 16; g++) {
            float4 t = vsrc[g];
            sm[VTO + (4*g+0)*128 + j] = t.x;
            sm[VTO + (4*g+1)*128 + j] = t.y;
            sm[VTO + (4*g+2)*128 + j] = t.z;
            sm[VTO + (4*g+3)*128 + j] = t.w;
        }
    }
    __syncthreads();

    int w = tid >> 5, l = tid & 31;

    // QK^T: warp w owns rows w*8..w*8+7; lane owns cols l+32*jj
    u64 acc[8][4];
#pragma unroll
    for (int i = 0; i < 8; i++)
#pragma unroll
        for (int j = 0; j < 4; j++) acc[i][j] = 0ULL;
#pragma unroll 4
    for (int dp2 = 0; dp2 < 16; dp2++) {
        ulonglong2 kk[4];
#pragma unroll
        for (int jj = 0; jj < 4; jj++)
            kk[jj] = *(const ulonglong2*)&sm[KTO + (dp2*128 + l + 32*jj)*4];
#pragma unroll
        for (int rr = 0; rr < 8; rr++) {
            ulonglong2 qq = *(const ulonglong2*)&sm[QSO + (w*8 + rr)*64 + dp2*4];
#pragma unroll
            for (int jj = 0; jj < 4; jj++) {
                fma2(acc[rr][jj], qq.x, kk[jj].x);
                fma2(acc[rr][jj], qq.y, kk[jj].y);
            }
        }
    }
    __syncthreads();   // q/k tiles free; probs region becomes writable

    // mask + softmax per row; write probs in float4-quad layout; emit logsumexp
#pragma unroll
    for (int rr = 0; rr < 8; rr++) {
        int i = w*8 + rr;
        int qi = qidx[i];
        float dv[4];
#pragma unroll
        for (int jj = 0; jj < 4; jj++) {
            float2 a = unpack2(acc[rr][jj]);
            float t = a.x + a.y;
            dv[jj] = (qi != kidx[l + 32*jj]) ? t : -1e5f;
        }
        float m = fmaxf(fmaxf(dv[0], dv[1]), fmaxf(dv[2], dv[3]));
#pragma unroll
        for (int off = 16; off; off >>= 1) m = fmaxf(m, __shfl_xor_sync(0xffffffffu, m, off));
        float p[4], ssum = 0.f;
#pragma unroll
        for (int jj = 0; jj < 4; jj++) { p[jj] = expf(dv[jj] - m); ssum += p[jj]; }
#pragma unroll
        for (int off = 16; off; off >>= 1) ssum += __shfl_xor_sync(0xffffffffu, ssum, off);
        float inv = 1.f / ssum;
#pragma unroll
        for (int jj = 0; jj < 4; jj++) {
            int cq = l + 32*jj;                 // col 0..127
            sm[PBO + (cq >> 2)*PBQ + i*4 + (cq & 3)] = p[jj] * inv;
        }
        if (l == 0) g_lsort[(size_t)bh*(NHH*SS) + c*64 + i] = logf(ssum) + m;
    }
    __syncthreads();

    // PV: lane owns rows l and l+32; warp owns dims w*8..w*8+7; jq over 32 quads
    u64 o0[8], o1[8];
#pragma unroll
    for (int dd = 0; dd < 8; dd++) { o0[dd] = 0ULL; o1[dd] = 0ULL; }
#pragma unroll 4
    for (int jq = 0; jq < 32; jq++) {
        ulonglong2 pr0 = *(const ulonglong2*)&sm[PBO + jq*PBQ + l*4];
        ulonglong2 pr1 = *(const ulonglong2*)&sm[PBO + jq*PBQ + (l+32)*4];
#pragma unroll
        for (int dd = 0; dd < 8; dd++) {
            ulonglong2 vv = *(const ulonglong2*)&sm[VTO + (w*8 + dd)*128 + jq*4];
            fma2(o0[dd], pr0.x, vv.x);
            fma2(o0[dd], pr0.y, vv.y);
            fma2(o1[dd], pr1.x, vv.x);
            fma2(o1[dd], pr1.y, vv.y);
        }
    }
    // direct global store: lane l -> rows l and l+32, dims w*8..w*8+7
    {
        float* base = g_osort + ((size_t)bh*(NHH*SS) + c*64)*DD + w*8;
        float r0[8], r1[8];
#pragma unroll
        for (int dd = 0; dd < 8; dd++) {
            float2 a = unpack2(o0[dd]); r0[dd] = a.x + a.y;
            float2 b2 = unpack2(o1[dd]); r1[dd] = b2.x + b2.y;
        }
        float* d0 = base + (size_t)l*DD;
        float* d1 = base + (size_t)(l+32)*DD;
        *(float4*)d0       = make_float4(r0[0], r0[1], r0[2], r0[3]);
        *(float4*)(d0 + 4) = make_float4(r0[4], r0[5], r0[6], r0[7]);
        *(float4*)d1       = make_float4(r1[0], r1[1], r1[2], r1[3]);
        *(float4*)(d1 + 4) = make_float4(r1[4], r1[5], r1[6], r1[7]);
    }
}

// ---------------- 5) key-side undo + combine rounds -------------------------
__global__ __launch_bounds__(256) void combine_kernel(float* __restrict__ out) {
    int row = blockIdx.x * 8 + (threadIdx.x >> 5);  // b*H*S rows
    int l = threadIdx.x & 31;
    int bh = row >> 12;
    int s = row & (SS - 1);
    int b = bh >> 3, h = bh & 7;
    float lg[NHH]; int up[NHH];
#pragma unroll
    for (int n = 0; n < NHH; n++) {
        int u = g_undo[((size_t)bh*NHH + n)*SS + s];
        up[n] = u;
        lg[n] = g_lsort[(size_t)bh*(NHH*SS) + n*SS + u];
    }
    float m = fmaxf(fmaxf(lg[0], lg[1]), fmaxf(lg[2], lg[3]));
    float w[NHH], wsum = 0.f;
#pragma unroll
    for (int n = 0; n < NHH; n++) { w[n] = expf(lg[n] - m); wsum += w[n]; }
    float inv = 1.f / wsum;
    float2 acc = make_float2(0.f, 0.f);
#pragma unroll
    for (int n = 0; n < NHH; n++) {
        float2 o = *(const float2*)&g_osort[((size_t)bh*(NHH*SS) + n*SS + up[n])*DD + l*2];
        acc.x += w[n]*o.x; acc.y += w[n]*o.y;
    }
    acc.x *= inv; acc.y *= inv;
    *(float2*)&out[((size_t)(b*SS + s))*(HH*DD) + h*DD + l*2] = acc;
}

// ---------------- launch -----------------------------------------------------
extern "C" void kernel_launch(void* const* d_in, const int* in_sizes, int n_in,
                              void* d_out, int out_size) {
    const float* dec = (const float*)d_in[0];
    const float* hid = (const float*)d_in[1];
    const float* wqk = (const float*)d_in[2];
    const float* wv  = (const float*)d_in[3];
    const float* rot = (const float*)d_in[4];
    float* out = (float*)d_out;

    cudaFuncSetAttribute(hash_gemmv_kernel, cudaFuncAttributeMaxDynamicSharedMemorySize, HASH_SMEM);
    cudaFuncSetAttribute(attn_kernel, cudaFuncAttributeMaxDynamicSharedMemorySize, SMEMF*4);

    gemm_kernel<<<dim3(8, 64, 2), 256>>>(dec, hid, wqk);       // Q, K
    hash_gemmv_kernel<<<2560, 256, HASH_SMEM>>>(hid, wv, rot); // V GEMM + hash
    sort_kernel<<<dim3(BB*HH*NHH, 2), 256>>>();
    attn_kernel<<<dim3(NCH, BB*HH), 256, SMEMF*4>>>();
    combine_kernel<<<BB*HH*SS/8, 256>>>(out);
}